// round 8
// baseline (speedup 1.0000x reference)
#include <cuda_runtime.h>
#include <cuda_bf16.h>

#define BEV_H 512
#define BEV_W 512
#define BEV_C 64
#define HW (BEV_H * BEV_W)   // 262144 = 2^18

// Scratch: last-writer (pillar index + 1) per BEV cell; 0 = empty.
// Zero-initialized at load; the gather kernel writes 0 back after reading,
// so the state self-restores for every graph replay (no memset needed).
__device__ int g_last[8 * HW];
// Zero row for empty cells (zero-initialized, never written).
__device__ __align__(16) float g_zero[BEV_C];

// ---------------------------------------------------------------------------
// Scatter: last-occurrence-wins via atomicMax of (pillar index + 1).
// ---------------------------------------------------------------------------
__global__ void bev_scatter_kernel(const int* __restrict__ coords, int P) {
    int t = blockIdx.x * blockDim.x + threadIdx.x;
    int p0 = t * 4;
    if (p0 + 3 < P) {
        const int4* c4 = reinterpret_cast<const int4*>(coords + p0 * 3);
        int4 a  = __ldg(c4 + 0);  // b0 r0 c0 b1
        int4 bb = __ldg(c4 + 1);  // r1 c1 b2 r2
        int4 cc = __ldg(c4 + 2);  // c2 b3 r3 c3
        int bs[4] = {a.x, a.w, bb.z, cc.y};
        int rs[4] = {a.y, bb.x, bb.w, cc.z};
        int cs[4] = {a.z, bb.y, cc.x, cc.w};
#pragma unroll
        for (int k = 0; k < 4; k++) {
            int r = min(max(rs[k], 0), BEV_H - 1);
            int c = min(max(cs[k], 0), BEV_W - 1);
            atomicMax(&g_last[bs[k] * HW + r * BEV_W + c], p0 + k + 1);
        }
    } else if (p0 < P) {
        for (int p = p0; p < P; p++) {
            int b = coords[3 * p + 0];
            int r = min(max(coords[3 * p + 1], 0), BEV_H - 1);
            int c = min(max(coords[3 * p + 2], 0), BEV_W - 1);
            atomicMax(&g_last[b * HW + r * BEV_W + c], p + 1);
        }
    }
}

// ---------------------------------------------------------------------------
// Gather + transpose. Warp-autonomous (only __syncwarp): each warp owns 32
// consecutive cells + a private 4KB smem slice. Two halves of 32 channels.
//   Produce (per half): two batches of 4 LDG.128 (keeps <=4 live float4 ->
//     low regs), STS.32 into swizzled tile word(ch,cell)=ch*32+(cell^8q):
//     banks cw+8(s^q), conflict-free.
//   Consume: 8x [LDS.128 + STG.128]; each STG writes 4 channels x one FULL
//     128B line (2 wf/cell stores).
// Also self-cleans g_last (writes 0 back) for the next graph replay.
// ---------------------------------------------------------------------------
__global__ void __launch_bounds__(256, 6) bev_gather_kernel(
    const float* __restrict__ feats,
    float* __restrict__ out) {
    __shared__ float sbuf[8][32 * 32];   // 4KB per warp, 32KB per CTA

    const int widx = threadIdx.x >> 5;
    const int l    = threadIdx.x & 31;
    const int q  = l & 3;     // producer: lane quarter in 4-lane row team
    const int cw = l >> 2;    // producer: 0..7 row-within-batch
    const int d  = l >> 3;    // consumer: channel sub-index 0..3
    const int c8 = l & 7;     // consumer: cell-quad index 0..7

    const int wgid = blockIdx.x * 8 + widx;
    const int base = wgid * 32;              // first cell (32-aligned, in-batch)
    const int b    = base >> 18;
    const int pos  = base & (HW - 1);

    // One coalesced g_last load per lane; reset to 0 for the next replay.
    const int myLast = __ldg(&g_last[base + l]);
    g_last[base + l] = 0;

    int lcv[4];
#pragma unroll
    for (int s = 0; s < 4; s++)
        lcv[s] = __shfl_sync(0xffffffffu, myLast, 8 * s + cw);

    float* buf  = sbuf[widx];
    float* outb = out + (size_t)b * (BEV_C * HW) + pos;

#pragma unroll
    for (int h = 0; h < 2; h++) {
        float4 A[4];
        // ---- batch 1: channels 32h + 4q (+0..3) ----
#pragma unroll
        for (int s = 0; s < 4; s++) {
            const float4* r = reinterpret_cast<const float4*>(
                lcv[s] > 0 ? feats + (size_t)(lcv[s] - 1) * BEV_C : g_zero);
            A[s] = __ldg(r + 8 * h + q);
        }
#pragma unroll
        for (int s = 0; s < 4; s++) {
            const int cs = cw + 8 * (s ^ q);
            float* pA = buf + (4 * q) * 32 + cs;
            pA[0 * 32] = A[s].x; pA[1 * 32] = A[s].y;
            pA[2 * 32] = A[s].z; pA[3 * 32] = A[s].w;
        }
        // ---- batch 2: channels 32h + 16 + 4q (+0..3) ----
#pragma unroll
        for (int s = 0; s < 4; s++) {
            const float4* r = reinterpret_cast<const float4*>(
                lcv[s] > 0 ? feats + (size_t)(lcv[s] - 1) * BEV_C : g_zero);
            A[s] = __ldg(r + 8 * h + q + 4);
        }
#pragma unroll
        for (int s = 0; s < 4; s++) {
            const int cs = cw + 8 * (s ^ q);
            float* pB = buf + (16 + 4 * q) * 32 + cs;
            pB[0 * 32] = A[s].x; pB[1 * 32] = A[s].y;
            pB[2 * 32] = A[s].z; pB[3 * 32] = A[s].w;
        }
        __syncwarp();

        // ---- consume: 8x (LDS.128 + STG.128), full-line stores ----
#pragma unroll
        for (int k = 0; k < 8; k++) {
            const int chh  = 4 * k + d;                       // 0..31
            const int addr = chh * 32 + ((c8 * 4) ^ (8 * (k & 3)));
            float4 v = *reinterpret_cast<const float4*>(buf + addr);
            *reinterpret_cast<float4*>(
                outb + (size_t)(32 * h + chh) * HW + c8 * 4) = v;
        }
        __syncwarp();   // protect buf before next half overwrites it
    }
}

extern "C" void kernel_launch(void* const* d_in, const int* in_sizes, int n_in,
                              void* d_out, int out_size) {
    const float* feats  = (const float*)d_in[0];   // (P, 64) float32
    const int*   coords = (const int*)d_in[1];     // (P, 3) int32
    float*       out    = (float*)d_out;           // (B, 64, 512, 512) float32

    int P = in_sizes[0] / BEV_C;
    int B = out_size / (BEV_C * HW);
    if (B > 8) B = 8;
    int ncells = B * HW;

    // 1) scatter (g_last is all-zero: initial load state, then restored by
    //    the gather kernel on every call)
    int nt = (P + 3) / 4;
    bev_scatter_kernel<<<(nt + 255) / 256, 256>>>(coords, P);

    // 2) gather + transpose + self-clean: 32 cells per warp, 8 warps per CTA
    bev_gather_kernel<<<ncells / 256, 256>>>(feats, out);
}

// round 9
// speedup vs baseline: 1.6661x; 1.6661x over previous
#include <cuda_runtime.h>
#include <cuda_bf16.h>

#define BEV_H 512
#define BEV_W 512
#define BEV_C 64
#define HW (BEV_H * BEV_W)   // 262144 = 2^18

// Scratch: last-writer pillar index per BEV cell (up to 8 batches).
__device__ int g_last[8 * HW];
// Zero row for empty cells (zero-initialized, never written).
__device__ __align__(16) float g_zero[BEV_C];

// ---------------------------------------------------------------------------
// Scatter: last-occurrence-wins via atomicMax on pillar index.
// ---------------------------------------------------------------------------
__global__ void bev_scatter_kernel(const int* __restrict__ coords, int P) {
    int t = blockIdx.x * blockDim.x + threadIdx.x;
    int p0 = t * 4;
    if (p0 + 3 < P) {
        const int4* c4 = reinterpret_cast<const int4*>(coords + p0 * 3);
        int4 a  = __ldg(c4 + 0);  // b0 r0 c0 b1
        int4 bb = __ldg(c4 + 1);  // r1 c1 b2 r2
        int4 cc = __ldg(c4 + 2);  // c2 b3 r3 c3
        int bs[4] = {a.x, a.w, bb.z, cc.y};
        int rs[4] = {a.y, bb.x, bb.w, cc.z};
        int cs[4] = {a.z, bb.y, cc.x, cc.w};
#pragma unroll
        for (int k = 0; k < 4; k++) {
            int r = min(max(rs[k], 0), BEV_H - 1);
            int c = min(max(cs[k], 0), BEV_W - 1);
            atomicMax(&g_last[bs[k] * HW + r * BEV_W + c], p0 + k);
        }
    } else if (p0 < P) {
        for (int p = p0; p < P; p++) {
            int b = coords[3 * p + 0];
            int r = min(max(coords[3 * p + 1], 0), BEV_H - 1);
            int c = min(max(coords[3 * p + 2], 0), BEV_W - 1);
            atomicMax(&g_last[b * HW + r * BEV_W + c], p);
        }
    }
}

// ---------------------------------------------------------------------------
// Gather + transpose. Warp-autonomous (only __syncwarp): warp owns 32 cells +
// a private 4KB smem slice. Two 32-channel halves, software-pipelined:
//   load h0 (8 LDG.128, all issued up front: MLP=8) -> STS h0 -> sync ->
//   load h1 (flies under h0's consume)              -> consume h0 -> sync ->
//   STS h1 -> sync -> consume h1.
// STS swizzle word(ch,cell)=ch*32+(cell^8q): banks cw+8(s^q), conflict-free.
// Consume k: lane(d=l>>3,c8=l&7) LDS.128 @ ch*32+((c8*4)^(8*(k&3))), STG.128
// = 4 channels x one FULL 128B line per instruction (2 wf/cell stores).
// ---------------------------------------------------------------------------
__device__ __forceinline__ const float4* row_ptr(const float* feats, int lc) {
    return reinterpret_cast<const float4*>(
        lc >= 0 ? feats + (size_t)lc * BEV_C : g_zero);
}

__global__ void __launch_bounds__(256, 5) bev_gather_kernel(
    const float* __restrict__ feats,
    float* __restrict__ out) {
    __shared__ float sbuf[8][32 * 32];   // 4KB per warp, 32KB per CTA

    const int widx = threadIdx.x >> 5;
    const int l    = threadIdx.x & 31;
    const int q  = l & 3;     // producer: lane quarter in 4-lane row team
    const int cw = l >> 2;    // producer: 0..7 row-within-batch
    const int d  = l >> 3;    // consumer: channel sub-index 0..3
    const int c8 = l & 7;     // consumer: cell-quad index 0..7

    const int wgid = blockIdx.x * 8 + widx;
    const int base = wgid * 32;              // first cell (32-aligned, in-batch)
    const int b    = base >> 18;
    const int pos  = base & (HW - 1);

    // One coalesced g_last load per lane; rows distributed via shuffle.
    const int myLast = __ldg(&g_last[base + l]);
    int lcv[4];
#pragma unroll
    for (int s = 0; s < 4; s++)
        lcv[s] = __shfl_sync(0xffffffffu, myLast, 8 * s + cw);

    float* buf  = sbuf[widx];
    float* outb = out + (size_t)b * (BEV_C * HW) + pos;

    // ---- load h0: all 8 LDG.128 issued before any consume (MLP=8) ----
    float4 A[8];
#pragma unroll
    for (int s = 0; s < 4; s++) {
        const float4* r = row_ptr(feats, lcv[s]);
        A[s]     = __ldg(r + q);        // channels 4q+e
        A[s + 4] = __ldg(r + q + 4);    // channels 16+4q+e
    }
    // ---- STS h0 ----
#pragma unroll
    for (int s = 0; s < 4; s++) {
        const int cs = cw + 8 * (s ^ q);
        float* pA = buf + (4 * q) * 32 + cs;
        pA[0 * 32] = A[s].x; pA[1 * 32] = A[s].y;
        pA[2 * 32] = A[s].z; pA[3 * 32] = A[s].w;
        float* pB = buf + (16 + 4 * q) * 32 + cs;
        pB[0 * 32] = A[s + 4].x; pB[1 * 32] = A[s + 4].y;
        pB[2 * 32] = A[s + 4].z; pB[3 * 32] = A[s + 4].w;
    }
    __syncwarp();

    // ---- load h1 now; flies while we consume h0 ----
    float4 B[8];
#pragma unroll
    for (int s = 0; s < 4; s++) {
        const float4* r = row_ptr(feats, lcv[s]);
        B[s]     = __ldg(r + q + 8);    // channels 32+4q+e
        B[s + 4] = __ldg(r + q + 12);   // channels 48+4q+e
    }

    // ---- consume h0: 8x (LDS.128 + STG.128) full-line stores ----
#pragma unroll
    for (int k = 0; k < 8; k++) {
        const int chh  = 4 * k + d;                       // 0..31
        const int addr = chh * 32 + ((c8 * 4) ^ (8 * (k & 3)));
        float4 v = *reinterpret_cast<const float4*>(buf + addr);
        *reinterpret_cast<float4*>(outb + (size_t)chh * HW + c8 * 4) = v;
    }
    __syncwarp();   // protect buf before h1 overwrites it

    // ---- STS h1 ----
#pragma unroll
    for (int s = 0; s < 4; s++) {
        const int cs = cw + 8 * (s ^ q);
        float* pA = buf + (4 * q) * 32 + cs;
        pA[0 * 32] = B[s].x; pA[1 * 32] = B[s].y;
        pA[2 * 32] = B[s].z; pA[3 * 32] = B[s].w;
        float* pB = buf + (16 + 4 * q) * 32 + cs;
        pB[0 * 32] = B[s + 4].x; pB[1 * 32] = B[s + 4].y;
        pB[2 * 32] = B[s + 4].z; pB[3 * 32] = B[s + 4].w;
    }
    __syncwarp();

    // ---- consume h1 ----
#pragma unroll
    for (int k = 0; k < 8; k++) {
        const int chh  = 4 * k + d;
        const int addr = chh * 32 + ((c8 * 4) ^ (8 * (k & 3)));
        float4 v = *reinterpret_cast<const float4*>(buf + addr);
        *reinterpret_cast<float4*>(outb + (size_t)(32 + chh) * HW + c8 * 4) = v;
    }
}

extern "C" void kernel_launch(void* const* d_in, const int* in_sizes, int n_in,
                              void* d_out, int out_size) {
    const float* feats  = (const float*)d_in[0];   // (P, 64) float32
    const int*   coords = (const int*)d_in[1];     // (P, 3) int32
    float*       out    = (float*)d_out;           // (B, 64, 512, 512) float32

    int P = in_sizes[0] / BEV_C;
    int B = out_size / (BEV_C * HW);
    if (B > 8) B = 8;
    int ncells = B * HW;

    // 1) init last-index grid to -1 (memset node; 0xFF bytes == -1 int)
    void* lastPtr = nullptr;
    cudaGetSymbolAddress(&lastPtr, g_last);
    cudaMemsetAsync(lastPtr, 0xFF, (size_t)ncells * sizeof(int), 0);

    // 2) scatter
    int nt = (P + 3) / 4;
    bev_scatter_kernel<<<(nt + 255) / 256, 256>>>(coords, P);

    // 3) gather + transpose: 32 cells per warp, 8 warps per CTA
    bev_gather_kernel<<<ncells / 256, 256>>>(feats, out);
}